// round 12
// baseline (speedup 1.0000x reference)
#include <cuda_runtime.h>
#include <cuda_bf16.h>
#include <cstdint>

#define D 128
#define P 8
#define NMAX 100000
#define LMAX 3
#define BS2 130   // Bs stride (words): ≡2 mod 8 -> float2 frag loads conflict-free

// Scratch (device globals — no allocation allowed)
__device__ float          g_ax[(size_t)NMAX * D];          // SpMM out (fp32)
__device__ __nv_bfloat16  g_xbf[(size_t)NMAX * D];         // x converted to bf16
__device__ __nv_bfloat16  g_hA[(size_t)NMAX * D];          // ping (bf16)
__device__ __nv_bfloat16  g_hB[(size_t)NMAX * D];          // pong (bf16)
__device__ int            g_row_ptr[NMAX + 1];
__device__ float          g_wwT[LMAX * D * D];             // [l][k][o]

// ---------------------------------------------------------------------------
__global__ void build_row_ptr_k(const int* __restrict__ edge_row, int E, int N) {
    int r = blockIdx.x * blockDim.x + threadIdx.x;
    if (r > N) return;
    int lo = 0, hi = E;
    while (lo < hi) {
        int mid = (lo + hi) >> 1;
        if (edge_row[mid] < r) lo = mid + 1; else hi = mid;
    }
    g_row_ptr[r] = lo;
}

// ---------------------------------------------------------------------------
__global__ void build_weights_k(const float* __restrict__ sp, const float* __restrict__ lw) {
    int l = blockIdx.x >> 7;
    int i = blockIdx.x & 127;
    int o = threadIdx.x;

    float w[P];
    float m = -1e30f;
#pragma unroll
    for (int p = 0; p < P; p++) { w[p] = lw[l * P + p]; m = fmaxf(m, w[p]); }
    float s = 0.f;
#pragma unroll
    for (int p = 0; p < P; p++) { w[p] = expf(w[p] - m); s += w[p]; }
    float inv = 1.f / s;

    const float* base = sp + (((size_t)l * D + o) * D + i) * P;
    float acc = 0.f;
#pragma unroll
    for (int p = 0; p < P; p++) acc = fmaf(base[p], w[p] * inv, acc);
    g_wwT[((size_t)l * D + i) * D + o] = acc;
}

// ---------------------------------------------------------------------------
__global__ void cvt_x_k(const float* __restrict__ x, int total4) {
    int i = blockIdx.x * blockDim.x + threadIdx.x;
    if (i >= total4) return;
    float4 v = __ldg(((const float4*)x) + i);
    __nv_bfloat162 a = __floats2bfloat162_rn(v.x, v.y);
    __nv_bfloat162 b = __floats2bfloat162_rn(v.z, v.w);
    ((__nv_bfloat162*)g_xbf)[2 * i]     = a;
    ((__nv_bfloat162*)g_xbf)[2 * i + 1] = b;
}

// ---------------------------------------------------------------------------
// SpMM over bf16 features: one warp per row, 4-edge unroll (MLP=12),
// fp32 accumulate, row-major fp32 output.
// ---------------------------------------------------------------------------
__device__ __forceinline__ void gather_fma(float4& acc, float v, uint2 u) {
    acc.x = fmaf(v, __uint_as_float(u.x << 16),          acc.x);
    acc.y = fmaf(v, __uint_as_float(u.x & 0xffff0000u),  acc.y);
    acc.z = fmaf(v, __uint_as_float(u.y << 16),          acc.z);
    acc.w = fmaf(v, __uint_as_float(u.y & 0xffff0000u),  acc.w);
}

__global__ void spmm_k(const int* __restrict__ col, const float* __restrict__ val,
                       const __nv_bfloat16* __restrict__ h, int N) {
    int warp = (int)((blockIdx.x * blockDim.x + threadIdx.x) >> 5);
    int lane = threadIdx.x & 31;
    if (warp >= N) return;
    int s = g_row_ptr[warp];
    int e = g_row_ptr[warp + 1];
    float4 a0 = make_float4(0.f, 0.f, 0.f, 0.f);
    float4 a1 = make_float4(0.f, 0.f, 0.f, 0.f);
    float4 a2 = make_float4(0.f, 0.f, 0.f, 0.f);
    float4 a3 = make_float4(0.f, 0.f, 0.f, 0.f);
    int k = s;
    for (; k + 3 < e; k += 4) {
        int   c0 = __ldg(col + k);
        int   c1 = __ldg(col + k + 1);
        int   c2 = __ldg(col + k + 2);
        int   c3 = __ldg(col + k + 3);
        float v0 = __ldg(val + k);
        float v1 = __ldg(val + k + 1);
        float v2 = __ldg(val + k + 2);
        float v3 = __ldg(val + k + 3);
        uint2 u0 = __ldg((const uint2*)(h + (size_t)c0 * D) + lane);
        uint2 u1 = __ldg((const uint2*)(h + (size_t)c1 * D) + lane);
        uint2 u2 = __ldg((const uint2*)(h + (size_t)c2 * D) + lane);
        uint2 u3 = __ldg((const uint2*)(h + (size_t)c3 * D) + lane);
        gather_fma(a0, v0, u0);
        gather_fma(a1, v1, u1);
        gather_fma(a2, v2, u2);
        gather_fma(a3, v3, u3);
    }
    for (; k < e; k++) {
        int   c0 = __ldg(col + k);
        float v0 = __ldg(val + k);
        uint2 u0 = __ldg((const uint2*)(h + (size_t)c0 * D) + lane);
        gather_fma(a0, v0, u0);
    }
    a0.x += a1.x + a2.x + a3.x;
    a0.y += a1.y + a2.y + a3.y;
    a0.z += a1.z + a2.z + a3.z;
    a0.w += a1.w + a2.w + a3.w;
    ((float4*)(g_ax + (size_t)warp * D))[lane] = a0;
}

// ---------------------------------------------------------------------------
__device__ __forceinline__ void mma_tf32(float (&d)[4],
                                         uint32_t a0, uint32_t a1, uint32_t a2, uint32_t a3,
                                         uint32_t b0, uint32_t b1) {
    asm volatile(
        "mma.sync.aligned.m16n8k8.row.col.f32.tf32.tf32.f32 "
        "{%0,%1,%2,%3},{%4,%5,%6,%7},{%8,%9},{%0,%1,%2,%3};"
        : "+f"(d[0]), "+f"(d[1]), "+f"(d[2]), "+f"(d[3])
        : "r"(a0), "r"(a1), "r"(a2), "r"(a3), "r"(b0), "r"(b1));
}

__device__ __forceinline__ uint32_t cvt_tf32(float x) {
    uint32_t r;
    asm("cvt.rn.tf32.f32 %0, %1;" : "=r"(r) : "f"(x));
    return r;
}

// ---------------------------------------------------------------------------
// Tensor-core GEMM (1xTF32, RN): block = 256 rows x 128 cols, 512 threads
// (16 warps/SM resident). Warp tile 32x64. k-permuted A LDG.128; B tf32
// k-permuted j-contiguous in smem. RELU layers emit bf16; final emits fp32.
// ---------------------------------------------------------------------------
template <bool RELU>
__global__ __launch_bounds__(512, 1) void gemm_tc(const float* __restrict__ A,
                                                  const float* __restrict__ B,
                                                  void* __restrict__ Cv, int N) {
    extern __shared__ float Bs[];   // [128][BS2], logical rows k-permuted

    const int tid = threadIdx.x;

    // stage B (128 x 128): permute k-rows, swap (j,g) within 64-halves, cvt tf32
#pragma unroll
    for (int i = tid; i < 128 * 32; i += 512) {
        int p  = i >> 5;
        int c4 = (i & 31) << 2;
        int pk = p & 15;
        int lpk = (pk >> 2) + ((pk & 1) << 2) + ((pk & 2) << 2);
        int lrow = (p & ~15) | lpk;
        float4 v = __ldg((const float4*)(B + p * 128 + c4));
        float vv[4] = {v.x, v.y, v.z, v.w};
#pragma unroll
        for (int e = 0; e < 4; e++) {
            int o = c4 + e;
            int hh = o >> 6;
            int j  = (o >> 3) & 7;
            int g  = o & 7;
            Bs[lrow * BS2 + (hh << 6) + (g << 3) + j] =
                __uint_as_float(cvt_tf32(vv[e]));
        }
    }
    __syncthreads();

    const int warp = tid >> 5;
    const int lane = tid & 31;
    const int g  = lane >> 2;
    const int t  = lane & 3;
    const int wr = warp >> 1;     // 0..7 row group of 32
    const int wc = warp & 1;      // 0..1 col group of 64

    const int row0 = blockIdx.x * 256 + wr * 32;

    int  r[4] = {row0 + g, row0 + g + 8, row0 + g + 16, row0 + g + 24};
    bool ok[4];
    const float* pA[4];
#pragma unroll
    for (int q = 0; q < 4; q++) {
        ok[q] = r[q] < N;
        pA[q] = A + (size_t)r[q] * D + 4 * t;
    }

    float acc[2][8][4];
#pragma unroll
    for (int s = 0; s < 2; s++)
#pragma unroll
        for (int j = 0; j < 8; j++)
#pragma unroll
            for (int q = 0; q < 4; q++) acc[s][j][q] = 0.f;

    const int bbase = wc * 64 + g * 8;

#pragma unroll
    for (int kb = 0; kb < 8; kb++) {
        float4 v[4];
#pragma unroll
        for (int q = 0; q < 4; q++)
            v[q] = ok[q] ? __ldg((const float4*)(pA[q] + kb * 16))
                         : make_float4(0.f, 0.f, 0.f, 0.f);

#pragma unroll
        for (int c = 0; c < 2; c++) {
            uint32_t a0[2], a1[2], a2[2], a3[2];
#pragma unroll
            for (int s = 0; s < 2; s++) {
                float f0 = (c == 0) ? v[2*s].x   : v[2*s].z;
                float f2 = (c == 0) ? v[2*s].y   : v[2*s].w;
                float f1 = (c == 0) ? v[2*s+1].x : v[2*s+1].z;
                float f3 = (c == 0) ? v[2*s+1].y : v[2*s+1].w;
                a0[s] = cvt_tf32(f0);
                a1[s] = cvt_tf32(f1);
                a2[s] = cvt_tf32(f2);
                a3[s] = cvt_tf32(f3);
            }

            const int kk = kb * 16 + c * 8;
            const float* brow0 = &Bs[(kk + t) * BS2 + bbase];
            const float* brow1 = &Bs[(kk + t + 4) * BS2 + bbase];
            uint2 b0p[4], b1p[4];
#pragma unroll
            for (int m = 0; m < 4; m++) {
                b0p[m] = *(const uint2*)(brow0 + 2 * m);
                b1p[m] = *(const uint2*)(brow1 + 2 * m);
            }

#pragma unroll
            for (int j = 0; j < 8; j++) {
                uint32_t b0 = (j & 1) ? b0p[j >> 1].y : b0p[j >> 1].x;
                uint32_t b1 = (j & 1) ? b1p[j >> 1].y : b1p[j >> 1].x;
#pragma unroll
                for (int s = 0; s < 2; s++)
                    mma_tf32(acc[s][j], a0[s], a1[s], a2[s], a3[s], b0, b1);
            }
        }
    }

    // epilogue
#pragma unroll
    for (int s = 0; s < 2; s++) {
        int rA = row0 + g + 16 * s;
        int rB = rA + 8;
        bool okA = rA < N;
        bool okB = rB < N;
#pragma unroll
        for (int j = 0; j < 8; j++) {
            float v0 = acc[s][j][0], v1 = acc[s][j][1];
            float v2 = acc[s][j][2], v3 = acc[s][j][3];
            int c = wc * 64 + j * 8 + 2 * t;
            if (RELU) {
                v0 = fmaxf(v0, 0.f); v1 = fmaxf(v1, 0.f);
                v2 = fmaxf(v2, 0.f); v3 = fmaxf(v3, 0.f);
                __nv_bfloat16* C = (__nv_bfloat16*)Cv;
                __nv_bfloat162 pA2 = __floats2bfloat162_rn(v0, v1);
                __nv_bfloat162 pB2 = __floats2bfloat162_rn(v2, v3);
                if (okA) *(__nv_bfloat162*)(C + (size_t)rA * D + c) = pA2;
                if (okB) *(__nv_bfloat162*)(C + (size_t)rB * D + c) = pB2;
            } else {
                float* C = (float*)Cv;
                if (okA) *(float2*)(C + (size_t)rA * D + c) = make_float2(v0, v1);
                if (okB) *(float2*)(C + (size_t)rB * D + c) = make_float2(v2, v3);
            }
        }
    }
}

// ---------------------------------------------------------------------------
extern "C" void kernel_launch(void* const* d_in, const int* in_sizes, int n_in,
                              void* d_out, int out_size) {
    const int*   edge_row  = (const int*)d_in[0];
    const int*   edge_col  = (const int*)d_in[1];
    const float* edge_vals = (const float*)d_in[2];
    const float* x         = (const float*)d_in[3];
    const float* sp        = (const float*)d_in[4];
    const float* lw        = (const float*)d_in[5];

    const int E = in_sizes[0];
    const int N = in_sizes[3] / D;
    const int L = in_sizes[5] / P;

    void *p_ax, *p_xbf, *p_hA, *p_hB, *p_ww;
    cudaGetSymbolAddress(&p_ax, g_ax);
    cudaGetSymbolAddress(&p_xbf, g_xbf);
    cudaGetSymbolAddress(&p_hA, g_hA);
    cudaGetSymbolAddress(&p_hB, g_hB);
    cudaGetSymbolAddress(&p_ww, g_wwT);

    const int smem_bytes = 128 * BS2 * 4;   // 66560
    cudaFuncSetAttribute(gemm_tc<true>,  cudaFuncAttributeMaxDynamicSharedMemorySize, smem_bytes);
    cudaFuncSetAttribute(gemm_tc<false>, cudaFuncAttributeMaxDynamicSharedMemorySize, smem_bytes);

    build_row_ptr_k<<<(N + 256) / 256, 256>>>(edge_row, E, N);
    build_weights_k<<<L * D, D>>>(sp, lw);
    const int total4 = N * D / 4;
    cvt_x_k<<<(total4 + 255) / 256, 256>>>(x, total4);

    __nv_bfloat16* bufs[2] = {(__nv_bfloat16*)p_hA, (__nv_bfloat16*)p_hB};
    const __nv_bfloat16* hin = (const __nv_bfloat16*)p_xbf;
    const int gemm_blocks = (N + 255) / 256;
    const int spmm_blocks = (N + 7) / 8;

    for (int l = 0; l < L; l++) {
        spmm_k<<<spmm_blocks, 256>>>(edge_col, edge_vals, hin, N);
        const float* Bm = (const float*)p_ww + (size_t)l * D * D;
        if (l < L - 1) {
            gemm_tc<true><<<gemm_blocks, 512, smem_bytes>>>((const float*)p_ax, Bm,
                                                            (void*)bufs[l & 1], N);
            hin = bufs[l & 1];
        } else {
            gemm_tc<false><<<gemm_blocks, 512, smem_bytes>>>((const float*)p_ax, Bm,
                                                             d_out, N);
        }
    }
}

// round 13
// speedup vs baseline: 1.2520x; 1.2520x over previous
#include <cuda_runtime.h>
#include <cuda_bf16.h>
#include <cstdint>

#define D 128
#define P 8
#define NMAX 100352    // padded to multiple of 32 (and 128) for swizzled ax
#define LMAX 3
#define BS2 130        // Bs stride (words): ≡2 mod 8 -> float2 frag loads conflict-free

// Scratch (device globals — no allocation allowed)
__device__ float          g_ax[(size_t)NMAX * D];          // SpMM out, MMA-swizzled fp32
__device__ __nv_bfloat16  g_xbf[(size_t)NMAX * D];         // x converted to bf16
__device__ __nv_bfloat16  g_hA[(size_t)NMAX * D];          // ping (bf16)
__device__ __nv_bfloat16  g_hB[(size_t)NMAX * D];          // pong (bf16)
__device__ int            g_row_ptr[NMAX + 1];
__device__ float          g_wwT[LMAX * D * D];             // [l][k][o]

// ax swizzle: word addr(r, c) with g32=r>>5, q=(r>>3)&3, g=r&7, kb=c>>4, w=c&15:
//   g32*4096 + q*1024 + kb*128 + g*16 + w
// GEMM per-(kb,q) warp load (lanes g,t; 16B each) is then 512B contiguous.

// ---------------------------------------------------------------------------
__global__ void build_row_ptr_k(const int* __restrict__ edge_row, int E, int N) {
    int r = blockIdx.x * blockDim.x + threadIdx.x;
    if (r > N) return;
    int lo = 0, hi = E;
    while (lo < hi) {
        int mid = (lo + hi) >> 1;
        if (edge_row[mid] < r) lo = mid + 1; else hi = mid;
    }
    g_row_ptr[r] = lo;
}

// ---------------------------------------------------------------------------
__global__ void build_weights_k(const float* __restrict__ sp, const float* __restrict__ lw) {
    int l = blockIdx.x >> 7;
    int i = blockIdx.x & 127;
    int o = threadIdx.x;

    float w[P];
    float m = -1e30f;
#pragma unroll
    for (int p = 0; p < P; p++) { w[p] = lw[l * P + p]; m = fmaxf(m, w[p]); }
    float s = 0.f;
#pragma unroll
    for (int p = 0; p < P; p++) { w[p] = expf(w[p] - m); s += w[p]; }
    float inv = 1.f / s;

    const float* base = sp + (((size_t)l * D + o) * D + i) * P;
    float acc = 0.f;
#pragma unroll
    for (int p = 0; p < P; p++) acc = fmaf(base[p], w[p] * inv, acc);
    g_wwT[((size_t)l * D + i) * D + o] = acc;
}

// ---------------------------------------------------------------------------
__global__ void cvt_x_k(const float* __restrict__ x, int total4) {
    int i = blockIdx.x * blockDim.x + threadIdx.x;
    if (i >= total4) return;
    float4 v = __ldg(((const float4*)x) + i);
    __nv_bfloat162 a = __floats2bfloat162_rn(v.x, v.y);
    __nv_bfloat162 b = __floats2bfloat162_rn(v.z, v.w);
    ((__nv_bfloat162*)g_xbf)[2 * i]     = a;
    ((__nv_bfloat162*)g_xbf)[2 * i + 1] = b;
}

// ---------------------------------------------------------------------------
// SpMM over bf16 features: one warp per row, 2-edge unroll (R10-proven),
// fp32 accumulate, output stored MMA-swizzled.
// ---------------------------------------------------------------------------
__global__ void spmm_k(const int* __restrict__ col, const float* __restrict__ val,
                       const __nv_bfloat16* __restrict__ h, int N) {
    int warp = (int)((blockIdx.x * blockDim.x + threadIdx.x) >> 5);
    int lane = threadIdx.x & 31;
    if (warp >= N) return;
    int s = g_row_ptr[warp];
    int e = g_row_ptr[warp + 1];
    float4 acc0 = make_float4(0.f, 0.f, 0.f, 0.f);
    float4 acc1 = make_float4(0.f, 0.f, 0.f, 0.f);
    int k = s;
    for (; k + 1 < e; k += 2) {
        int   c0 = __ldg(col + k);
        int   c1 = __ldg(col + k + 1);
        float v0 = __ldg(val + k);
        float v1 = __ldg(val + k + 1);
        uint2 u0 = __ldg((const uint2*)(h + (size_t)c0 * D) + lane);
        uint2 u1 = __ldg((const uint2*)(h + (size_t)c1 * D) + lane);
        acc0.x = fmaf(v0, __uint_as_float(u0.x << 16),         acc0.x);
        acc0.y = fmaf(v0, __uint_as_float(u0.x & 0xffff0000u), acc0.y);
        acc0.z = fmaf(v0, __uint_as_float(u0.y << 16),         acc0.z);
        acc0.w = fmaf(v0, __uint_as_float(u0.y & 0xffff0000u), acc0.w);
        acc1.x = fmaf(v1, __uint_as_float(u1.x << 16),         acc1.x);
        acc1.y = fmaf(v1, __uint_as_float(u1.x & 0xffff0000u), acc1.y);
        acc1.z = fmaf(v1, __uint_as_float(u1.y << 16),         acc1.z);
        acc1.w = fmaf(v1, __uint_as_float(u1.y & 0xffff0000u), acc1.w);
    }
    if (k < e) {
        int   c0 = __ldg(col + k);
        float v0 = __ldg(val + k);
        uint2 u0 = __ldg((const uint2*)(h + (size_t)c0 * D) + lane);
        acc0.x = fmaf(v0, __uint_as_float(u0.x << 16),         acc0.x);
        acc0.y = fmaf(v0, __uint_as_float(u0.x & 0xffff0000u), acc0.y);
        acc0.z = fmaf(v0, __uint_as_float(u0.y << 16),         acc0.z);
        acc0.w = fmaf(v0, __uint_as_float(u0.y & 0xffff0000u), acc0.w);
    }
    acc0.x += acc1.x; acc0.y += acc1.y; acc0.z += acc1.z; acc0.w += acc1.w;

    // swizzled store: lane owns cols 4*lane..4*lane+3 -> kb = lane>>2, w = (lane&3)*4
    int r = warp;
    size_t off = ((size_t)(r >> 5) << 12) + (size_t)(((r >> 3) & 3) << 10)
               + ((lane >> 2) << 7) + ((r & 7) << 4) + ((lane & 3) << 2);
    *(float4*)(g_ax + off) = acc0;
}

// ---------------------------------------------------------------------------
__device__ __forceinline__ void mma_tf32(float (&d)[4],
                                         uint32_t a0, uint32_t a1, uint32_t a2, uint32_t a3,
                                         uint32_t b0, uint32_t b1) {
    asm volatile(
        "mma.sync.aligned.m16n8k8.row.col.f32.tf32.tf32.f32 "
        "{%0,%1,%2,%3},{%4,%5,%6,%7},{%8,%9},{%0,%1,%2,%3};"
        : "+f"(d[0]), "+f"(d[1]), "+f"(d[2]), "+f"(d[3])
        : "r"(a0), "r"(a1), "r"(a2), "r"(a3), "r"(b0), "r"(b1));
}

__device__ __forceinline__ uint32_t cvt_tf32(float x) {
    uint32_t r;
    asm("cvt.rn.tf32.f32 %0, %1;" : "=r"(r) : "f"(x));
    return r;
}

// ---------------------------------------------------------------------------
// Tensor-core GEMM (1xTF32, RN): block = 128 rows x 128 cols, 256 threads,
// warp 32x64, 2 blocks/SM. A read from swizzled g_ax: per-(kb,q) warp load is
// one contiguous 512B LDG.128 (4 wavefronts). Explicit A prefetch across kb.
// B tf32 k-permuted j-contiguous in smem. RELU layers emit bf16; final fp32.
// ---------------------------------------------------------------------------
template <bool RELU>
__global__ __launch_bounds__(256, 2) void gemm_tc(const float* __restrict__ A,
                                                  const float* __restrict__ B,
                                                  void* __restrict__ Cv, int N) {
    extern __shared__ float Bs[];   // [128][BS2], logical rows k-permuted

    const int tid = threadIdx.x;

    // stage B (128 x 128): permute k-rows, swap (j,g) within 64-halves, cvt tf32
#pragma unroll
    for (int i = tid; i < 128 * 32; i += 256) {
        int p  = i >> 5;
        int c4 = (i & 31) << 2;
        int pk = p & 15;
        int lpk = (pk >> 2) + ((pk & 1) << 2) + ((pk & 2) << 2);
        int lrow = (p & ~15) | lpk;
        float4 v = __ldg((const float4*)(B + p * 128 + c4));
        float vv[4] = {v.x, v.y, v.z, v.w};
#pragma unroll
        for (int e = 0; e < 4; e++) {
            int o = c4 + e;
            int hh = o >> 6;
            int j  = (o >> 3) & 7;
            int g  = o & 7;
            Bs[lrow * BS2 + (hh << 6) + (g << 3) + j] =
                __uint_as_float(cvt_tf32(vv[e]));
        }
    }
    __syncthreads();

    const int warp = tid >> 5;
    const int lane = tid & 31;
    const int g  = lane >> 2;
    const int t  = lane & 3;
    const int wr = warp >> 1;
    const int wc = warp & 1;

    const int row0 = blockIdx.x * 128 + wr * 32;   // 32-aligned

    bool ok[4];
    const float* pA[4];
#pragma unroll
    for (int q = 0; q < 4; q++) {
        ok[q] = (row0 + 8 * q + g) < N;
        // swizzled base: g32*4096 + q*1024 + g*16 + t*4 ; + kb*128 in loop
        pA[q] = A + (((size_t)(row0 >> 5)) << 12) + (q << 10) + (g << 4) + (t << 2);
    }

    float acc[2][8][4];
#pragma unroll
    for (int s = 0; s < 2; s++)
#pragma unroll
        for (int j = 0; j < 8; j++)
#pragma unroll
            for (int q = 0; q < 4; q++) acc[s][j][q] = 0.f;

    const int bbase = wc * 64 + g * 8;

    // prefetch kb=0
    float4 v[4];
#pragma unroll
    for (int q = 0; q < 4; q++)
        v[q] = ok[q] ? __ldg((const float4*)(pA[q])) : make_float4(0.f, 0.f, 0.f, 0.f);

#pragma unroll
    for (int kb = 0; kb < 8; kb++) {
        // prefetch next kb
        float4 vn[4];
        if (kb < 7) {
#pragma unroll
            for (int q = 0; q < 4; q++)
                vn[q] = ok[q] ? __ldg((const float4*)(pA[q] + (kb + 1) * 128))
                              : make_float4(0.f, 0.f, 0.f, 0.f);
        }

#pragma unroll
        for (int c = 0; c < 2; c++) {
            uint32_t a0[2], a1[2], a2[2], a3[2];
#pragma unroll
            for (int s = 0; s < 2; s++) {
                float f0 = (c == 0) ? v[2*s].x   : v[2*s].z;
                float f2 = (c == 0) ? v[2*s].y   : v[2*s].w;
                float f1 = (c == 0) ? v[2*s+1].x : v[2*s+1].z;
                float f3 = (c == 0) ? v[2*s+1].y : v[2*s+1].w;
                a0[s] = cvt_tf32(f0);
                a1[s] = cvt_tf32(f1);
                a2[s] = cvt_tf32(f2);
                a3[s] = cvt_tf32(f3);
            }

            const int kk = kb * 16 + c * 8;
            const float* brow0 = &Bs[(kk + t) * BS2 + bbase];
            const float* brow1 = &Bs[(kk + t + 4) * BS2 + bbase];
            uint2 b0p[4], b1p[4];
#pragma unroll
            for (int m = 0; m < 4; m++) {
                b0p[m] = *(const uint2*)(brow0 + 2 * m);
                b1p[m] = *(const uint2*)(brow1 + 2 * m);
            }

#pragma unroll
            for (int j = 0; j < 8; j++) {
                uint32_t b0 = (j & 1) ? b0p[j >> 1].y : b0p[j >> 1].x;
                uint32_t b1 = (j & 1) ? b1p[j >> 1].y : b1p[j >> 1].x;
#pragma unroll
                for (int s = 0; s < 2; s++)
                    mma_tf32(acc[s][j], a0[s], a1[s], a2[s], a3[s], b0, b1);
            }
        }

        if (kb < 7) {
#pragma unroll
            for (int q = 0; q < 4; q++) v[q] = vn[q];
        }
    }

    // epilogue (row-major outputs)
#pragma unroll
    for (int s = 0; s < 2; s++) {
        int rA = row0 + g + 16 * s;
        int rB = rA + 8;
        bool okA = rA < N;
        bool okB = rB < N;
#pragma unroll
        for (int j = 0; j < 8; j++) {
            float v0 = acc[s][j][0], v1 = acc[s][j][1];
            float v2 = acc[s][j][2], v3 = acc[s][j][3];
            int c = wc * 64 + j * 8 + 2 * t;
            if (RELU) {
                v0 = fmaxf(v0, 0.f); v1 = fmaxf(v1, 0.f);
                v2 = fmaxf(v2, 0.f); v3 = fmaxf(v3, 0.f);
                __nv_bfloat16* C = (__nv_bfloat16*)Cv;
                __nv_bfloat162 pA2 = __floats2bfloat162_rn(v0, v1);
                __nv_bfloat162 pB2 = __floats2bfloat162_rn(v2, v3);
                if (okA) *(__nv_bfloat162*)(C + (size_t)rA * D + c) = pA2;
                if (okB) *(__nv_bfloat162*)(C + (size_t)rB * D + c) = pB2;
            } else {
                float* C = (float*)Cv;
                if (okA) *(float2*)(C + (size_t)rA * D + c) = make_float2(v0, v1);
                if (okB) *(float2*)(C + (size_t)rB * D + c) = make_float2(v2, v3);
            }
        }
    }
}

// ---------------------------------------------------------------------------
extern "C" void kernel_launch(void* const* d_in, const int* in_sizes, int n_in,
                              void* d_out, int out_size) {
    const int*   edge_row  = (const int*)d_in[0];
    const int*   edge_col  = (const int*)d_in[1];
    const float* edge_vals = (const float*)d_in[2];
    const float* x         = (const float*)d_in[3];
    const float* sp        = (const float*)d_in[4];
    const float* lw        = (const float*)d_in[5];

    const int E = in_sizes[0];
    const int N = in_sizes[3] / D;
    const int L = in_sizes[5] / P;

    void *p_ax, *p_xbf, *p_hA, *p_hB, *p_ww;
    cudaGetSymbolAddress(&p_ax, g_ax);
    cudaGetSymbolAddress(&p_xbf, g_xbf);
    cudaGetSymbolAddress(&p_hA, g_hA);
    cudaGetSymbolAddress(&p_hB, g_hB);
    cudaGetSymbolAddress(&p_ww, g_wwT);

    const int smem_bytes = 128 * BS2 * 4;   // 66560
    cudaFuncSetAttribute(gemm_tc<true>,  cudaFuncAttributeMaxDynamicSharedMemorySize, smem_bytes);
    cudaFuncSetAttribute(gemm_tc<false>, cudaFuncAttributeMaxDynamicSharedMemorySize, smem_bytes);

    build_row_ptr_k<<<(N + 256) / 256, 256>>>(edge_row, E, N);
    build_weights_k<<<L * D, D>>>(sp, lw);
    const int total4 = N * D / 4;
    cvt_x_k<<<(total4 + 255) / 256, 256>>>(x, total4);

    __nv_bfloat16* bufs[2] = {(__nv_bfloat16*)p_hA, (__nv_bfloat16*)p_hB};
    const __nv_bfloat16* hin = (const __nv_bfloat16*)p_xbf;
    const int gemm_blocks = (N + 127) / 128;
    const int spmm_blocks = (N + 7) / 8;

    for (int l = 0; l < L; l++) {
        spmm_k<<<spmm_blocks, 256>>>(edge_col, edge_vals, hin, N);
        const float* Bm = (const float*)p_ww + (size_t)l * D * D;
        if (l < L - 1) {
            gemm_tc<true><<<gemm_blocks, 256, smem_bytes>>>((const float*)p_ax, Bm,
                                                            (void*)bufs[l & 1], N);
            hin = bufs[l & 1];
        } else {
            gemm_tc<false><<<gemm_blocks, 256, smem_bytes>>>((const float*)p_ax, Bm,
                                                             d_out, N);
        }
    }
}